// round 6
// baseline (speedup 1.0000x reference)
#include <cuda_runtime.h>
#include <math.h>

#define NNODES 65536
#define EMB 128
#define HEADS 4
#define HDIM 32
#define KCTX 16
#define FF 256
#define SCALE 0.17677669529663687f   // 1/sqrt(32)
#define LN_EPS 1e-5f

// ---------------- scratch (static device arrays; no allocation) ----------------
__device__ float g_qt[(size_t)NNODES * 512];   // q~ per node: [n][h][e]  (scale folded in)
__device__ float g_h1[(size_t)NNODES * 128];   // post-ln1 hidden
__device__ float g_ff[(size_t)NNODES * 256];   // gelu(ffn1)

// ---------------- packed fp32x2 FMA (Blackwell FFMA2, PTX-only) ----------------
__device__ __forceinline__ float2 ffma2(float2 a, float2 b, float2 c) {
    float2 d;
    asm("{\n\t"
        ".reg .b64 ra, rb, rc, rd;\n\t"
        "mov.b64 ra, {%2,%3};\n\t"
        "mov.b64 rb, {%4,%5};\n\t"
        "mov.b64 rc, {%6,%7};\n\t"
        "fma.rn.f32x2 rd, ra, rb, rc;\n\t"
        "mov.b64 {%0,%1}, rd;\n\t"
        "}"
        : "=f"(d.x), "=f"(d.y)
        : "f"(a.x), "f"(a.y), "f"(b.x), "f"(b.y), "f"(c.x), "f"(c.y));
    return d;
}

// =====================================================================
// K1: q~[n,h,e] = SCALE * sum_d Wk[h*32+d][e] * Q[n][h*32+d],
//     Q[n][o]   = sum_i Wq[o][i] * x[n][i]
// 32 nodes / CTA, 256 threads (8 warps * 4 nodes), 1 warp = 4 nodes.
// smem: WqT[128][132] | Wk[128][128] | xs[32][132] | Qs[32][128]
// =====================================================================
__global__ __launch_bounds__(256, 1)
void k1_qt(const float* __restrict__ x, const float* __restrict__ Wq,
           const float* __restrict__ Wk, float* __restrict__ qt)
{
    extern __shared__ float sm[];
    float* WqT = sm;                       // 128*132 = 16896
    float* Wks = WqT + 128 * 132;          // 16384
    float* xs  = Wks + 128 * 128;          // 32*132 = 4224
    float* Qs  = xs + 32 * 132;            // 4096
    const int tid = threadIdx.x;

    for (int idx = tid; idx < 128 * 128; idx += 256) {
        int o = idx >> 7, i = idx & 127;
        WqT[i * 132 + o] = Wq[idx];
    }
    {
        const float4* s4 = (const float4*)Wk;
        float4* d4 = (float4*)Wks;
        for (int idx = tid; idx < 128 * 128 / 4; idx += 256) d4[idx] = s4[idx];
    }
    const int nb0 = blockIdx.x * 32;
    {
        const float4* x4 = (const float4*)(x + (size_t)nb0 * 128);
        for (int idx = tid; idx < 32 * 32; idx += 256) {
            int n = idx >> 5, c = idx & 31;
            *(float4*)(xs + n * 132 + c * 4) = x4[idx];
        }
    }
    __syncthreads();

    const int warp = tid >> 5, lane = tid & 31;
    const int nb = warp * 4;
    const int o4 = lane * 4;

    // ---- Q = Wq x ----
    float2 acc[4][2];
#pragma unroll
    for (int j = 0; j < 4; j++) { acc[j][0] = make_float2(0.f, 0.f); acc[j][1] = make_float2(0.f, 0.f); }
#pragma unroll 4
    for (int i = 0; i < 128; i++) {
        float4 w = *(float4*)(WqT + i * 132 + o4);
        float2 wl = make_float2(w.x, w.y), wh = make_float2(w.z, w.w);
#pragma unroll
        for (int j = 0; j < 4; j++) {
            float xv = xs[(nb + j) * 132 + i];
            float2 xd = make_float2(xv, xv);
            acc[j][0] = ffma2(wl, xd, acc[j][0]);
            acc[j][1] = ffma2(wh, xd, acc[j][1]);
        }
    }
#pragma unroll
    for (int j = 0; j < 4; j++)
        *(float4*)(Qs + (nb + j) * 128 + o4) =
            make_float4(acc[j][0].x, acc[j][0].y, acc[j][1].x, acc[j][1].y);
    __syncthreads();

    // ---- q~ = SCALE * Wk_h^T Q_h ----
    for (int h = 0; h < 4; h++) {
        float2 a[4][2];
#pragma unroll
        for (int j = 0; j < 4; j++) { a[j][0] = make_float2(0.f, 0.f); a[j][1] = make_float2(0.f, 0.f); }
#pragma unroll 4
        for (int d = 0; d < 32; d++) {
            int o = h * 32 + d;
            float4 w = *(float4*)(Wks + o * 128 + o4);
            float2 wl = make_float2(w.x, w.y), wh = make_float2(w.z, w.w);
#pragma unroll
            for (int j = 0; j < 4; j++) {
                float qv = Qs[(nb + j) * 128 + o];
                float2 qd = make_float2(qv, qv);
                a[j][0] = ffma2(wl, qd, a[j][0]);
                a[j][1] = ffma2(wh, qd, a[j][1]);
            }
        }
#pragma unroll
        for (int j = 0; j < 4; j++) {
            size_t base = ((size_t)(nb0 + nb + j)) * 512 + h * 128 + o4;
            *(float4*)(qt + base) = make_float4(a[j][0].x * SCALE, a[j][0].y * SCALE,
                                                a[j][1].x * SCALE, a[j][1].y * SCALE);
        }
    }
}

// =====================================================================
// K2: fused attention: scores -> softmax -> weighted ctx -> Wv -> Wo
//     -> +x -> LayerNorm1 -> h1.  One warp per node, 8 groups/CTA.
// smem: WvT[128][132] | WoT[128][132] | cs[8][16][132] | u[8][4][132]
//       | ss[8][4][16] | os[8][132] | ln1_g[128] | ln1_b[128]
// =====================================================================
__global__ __launch_bounds__(256, 1)
void k2_attn(const float* __restrict__ x, const float* __restrict__ ctx,
             const float* __restrict__ Wv, const float* __restrict__ Wo,
             const float* __restrict__ ln1g, const float* __restrict__ ln1b,
             const float* __restrict__ qt, float* __restrict__ h1out)
{
    extern __shared__ float sm[];
    float* WvT = sm;                         // 16896
    float* WoT = WvT + 128 * 132;            // 16896
    float* cs  = WoT + 128 * 132;            // 8*16*132 = 16896
    float* u   = cs + 8 * 16 * 132;          // 8*4*132  = 4224 (qt, later wctx)
    float* ss  = u + 8 * 4 * 132;            // 8*4*16   = 512
    float* os  = ss + 8 * 64;                // 8*132    = 1056
    float* lg  = os + 8 * 132;               // 128
    float* lb  = lg + 128;                   // 128
    const int tid = threadIdx.x;

    for (int idx = tid; idx < 128 * 128; idx += 256) {
        int o = idx >> 7, e = idx & 127;
        WvT[e * 132 + o] = Wv[idx];
        WoT[e * 132 + o] = Wo[idx];
    }
    if (tid < 128) { lg[tid] = ln1g[tid]; lb[tid] = ln1b[tid]; }
    __syncthreads();

    const int w = tid >> 5, lane = tid & 31;
    float* csw = cs + w * 16 * 132;
    float* uw  = u + w * 4 * 132;
    float* ssw = ss + w * 64;
    float* osw = os + w * 132;
    const int o4 = lane * 4;

    for (int g = 0; g < 8; g++) {
        const int node = blockIdx.x * 64 + g * 8 + w;

        // load ctx tile (16x128) and q~ (4x128) for this node
        const float4* c4 = (const float4*)(ctx + (size_t)node * 2048);
        for (int t = lane; t < 512; t += 32) {
            int k = t >> 5, c = t & 31;
            *(float4*)(csw + k * 132 + c * 4) = c4[t];
        }
        const float4* q4 = (const float4*)(qt + (size_t)node * 512);
        for (int t = lane; t < 128; t += 32) {
            int h = t >> 5, c = t & 31;
            *(float4*)(uw + h * 132 + c * 4) = q4[t];
        }
        __syncwarp();

        // ---- scores[h][k] = q~_h . ctx_k  (2 pairs per lane) ----
        {
            int h = lane >> 3, k0 = (lane & 7) * 2;
            const float* qrow = uw + h * 132;
            const float* c0 = csw + k0 * 132;
            const float* c1 = c0 + 132;
            float s0 = 0.f, s1 = 0.f;
#pragma unroll 4
            for (int e = 0; e < 128; e++) {
                float q = qrow[e];
                s0 = fmaf(q, c0[e], s0);
                s1 = fmaf(q, c1[e], s1);
            }
            ssw[h * 16 + k0]     = s0;
            ssw[h * 16 + k0 + 1] = s1;
        }
        __syncwarp();

        // ---- softmax over k (one head per lane 0..3) ----
        if (lane < 4) {
            float* r = ssw + lane * 16;
            float m = r[0];
#pragma unroll
            for (int k = 1; k < 16; k++) m = fmaxf(m, r[k]);
            float sum = 0.f;
#pragma unroll
            for (int k = 0; k < 16; k++) { float ev = __expf(r[k] - m); r[k] = ev; sum += ev; }
            float inv = 1.f / sum;
#pragma unroll
            for (int k = 0; k < 16; k++) r[k] *= inv;
        }
        __syncwarp();

        // ---- weighted ctx: wctx[h][e] = sum_k attn[h][k] ctx[k][e] ----
        float wc[4][4];
#pragma unroll
        for (int h = 0; h < 4; h++)
#pragma unroll
            for (int m = 0; m < 4; m++) wc[h][m] = 0.f;
#pragma unroll
        for (int k = 0; k < 16; k++) {
            const float* crow = csw + k * 132;
            float v0 = crow[lane], v1 = crow[lane + 32], v2 = crow[lane + 64], v3 = crow[lane + 96];
#pragma unroll
            for (int h = 0; h < 4; h++) {
                float a = ssw[h * 16 + k];
                wc[h][0] = fmaf(a, v0, wc[h][0]);
                wc[h][1] = fmaf(a, v1, wc[h][1]);
                wc[h][2] = fmaf(a, v2, wc[h][2]);
                wc[h][3] = fmaf(a, v3, wc[h][3]);
            }
        }
        __syncwarp();   // all lanes done reading uw (q~) before overwrite
#pragma unroll
        for (int h = 0; h < 4; h++) {
            uw[h * 132 + lane]      = wc[h][0];
            uw[h * 132 + lane + 32] = wc[h][1];
            uw[h * 132 + lane + 64] = wc[h][2];
            uw[h * 132 + lane + 96] = wc[h][3];
        }
        __syncwarp();

        // ---- o[o4..] = Wv_h . wctx_h ----
        {
            const int ho = lane >> 3;          // head of outputs o4..o4+3
            const float* wrow = uw + ho * 132;
            float2 a0 = make_float2(0.f, 0.f), a1 = make_float2(0.f, 0.f);
#pragma unroll 4
            for (int e = 0; e < 128; e++) {
                float4 wv = *(float4*)(WvT + e * 132 + o4);
                float wcv = wrow[e];
                float2 wd = make_float2(wcv, wcv);
                a0 = ffma2(make_float2(wv.x, wv.y), wd, a0);
                a1 = ffma2(make_float2(wv.z, wv.w), wd, a1);
            }
            *(float4*)(osw + o4) = make_float4(a0.x, a0.y, a1.x, a1.y);
        }
        __syncwarp();

        // ---- attnout = Wo . o ; residual + LayerNorm1 ----
        {
            float2 b0 = make_float2(0.f, 0.f), b1 = make_float2(0.f, 0.f);
#pragma unroll 4
            for (int j = 0; j < 128; j++) {
                float4 wo = *(float4*)(WoT + j * 132 + o4);
                float ov = osw[j];
                float2 od = make_float2(ov, ov);
                b0 = ffma2(make_float2(wo.x, wo.y), od, b0);
                b1 = ffma2(make_float2(wo.z, wo.w), od, b1);
            }
            float4 xv = *(const float4*)(x + (size_t)node * 128 + o4);
            float r0 = xv.x + b0.x, r1 = xv.y + b0.y, r2 = xv.z + b1.x, r3 = xv.w + b1.y;
            float s  = r0 + r1 + r2 + r3;
            float sq = fmaf(r0, r0, fmaf(r1, r1, fmaf(r2, r2, r3 * r3)));
#pragma unroll
            for (int off = 16; off > 0; off >>= 1) {
                s  += __shfl_xor_sync(0xffffffffu, s, off);
                sq += __shfl_xor_sync(0xffffffffu, sq, off);
            }
            float mu  = s * (1.f / 128.f);
            float var = sq * (1.f / 128.f) - mu * mu;
            float rstd = rsqrtf(var + LN_EPS);
            float4 gv = *(float4*)(lg + o4);
            float4 bv = *(float4*)(lb + o4);
            float h0 = (r0 - mu) * rstd * gv.x + bv.x;
            float h1v = (r1 - mu) * rstd * gv.y + bv.y;
            float h2 = (r2 - mu) * rstd * gv.z + bv.z;
            float h3 = (r3 - mu) * rstd * gv.w + bv.w;
            *(float4*)(h1out + (size_t)node * 128 + o4) = make_float4(h0, h1v, h2, h3);
        }
        __syncwarp();
    }
}

// =====================================================================
// K3: ff[n][f] = gelu_exact( W1 h1 + b1 ), f in [0,256)
// smem: W1T[128][260] | h1s[32][132] | b1[256]
// =====================================================================
__global__ __launch_bounds__(256, 1)
void k3_ffn1(const float* __restrict__ h1, const float* __restrict__ W1,
             const float* __restrict__ b1, float* __restrict__ ff)
{
    extern __shared__ float sm[];
    float* W1T = sm;                   // 128*260 = 33280
    float* h1s = W1T + 128 * 260;      // 32*132 = 4224
    float* b1s = h1s + 32 * 132;       // 256
    const int tid = threadIdx.x;

    for (int idx = tid; idx < 256 * 128; idx += 256) {
        int f = idx >> 7, e = idx & 127;
        W1T[e * 260 + f] = W1[idx];
    }
    if (tid < 256) b1s[tid] = b1[tid];
    const int nb0 = blockIdx.x * 32;
    {
        const float4* s4 = (const float4*)(h1 + (size_t)nb0 * 128);
        for (int idx = tid; idx < 32 * 32; idx += 256) {
            int n = idx >> 5, c = idx & 31;
            *(float4*)(h1s + n * 132 + c * 4) = s4[idx];
        }
    }
    __syncthreads();

    const int warp = tid >> 5, lane = tid & 31;
    const int nb = warp * 4;
    const int f4 = lane * 4;

    float2 acc[4][4];
#pragma unroll
    for (int j = 0; j < 4; j++)
#pragma unroll
        for (int m = 0; m < 4; m++) acc[j][m] = make_float2(0.f, 0.f);

#pragma unroll 4
    for (int e = 0; e < 128; e++) {
        float4 wa = *(float4*)(W1T + e * 260 + f4);
        float4 wb = *(float4*)(W1T + e * 260 + f4 + 128);
        float2 al = make_float2(wa.x, wa.y), ah = make_float2(wa.z, wa.w);
        float2 bl = make_float2(wb.x, wb.y), bh = make_float2(wb.z, wb.w);
#pragma unroll
        for (int j = 0; j < 4; j++) {
            float hv = h1s[(nb + j) * 132 + e];
            float2 hd = make_float2(hv, hv);
            acc[j][0] = ffma2(al, hd, acc[j][0]);
            acc[j][1] = ffma2(ah, hd, acc[j][1]);
            acc[j][2] = ffma2(bl, hd, acc[j][2]);
            acc[j][3] = ffma2(bh, hd, acc[j][3]);
        }
    }

#pragma unroll
    for (int j = 0; j < 4; j++) {
        float v[8];
        v[0] = acc[j][0].x + b1s[f4];       v[1] = acc[j][0].y + b1s[f4 + 1];
        v[2] = acc[j][1].x + b1s[f4 + 2];   v[3] = acc[j][1].y + b1s[f4 + 3];
        v[4] = acc[j][2].x + b1s[f4 + 128]; v[5] = acc[j][2].y + b1s[f4 + 129];
        v[6] = acc[j][3].x + b1s[f4 + 130]; v[7] = acc[j][3].y + b1s[f4 + 131];
#pragma unroll
        for (int m = 0; m < 8; m++)
            v[m] = 0.5f * v[m] * (1.0f + erff(v[m] * 0.70710678118654752f));
        size_t base = (size_t)(nb0 + nb + j) * 256;
        *(float4*)(ff + base + f4)       = make_float4(v[0], v[1], v[2], v[3]);
        *(float4*)(ff + base + f4 + 128) = make_float4(v[4], v[5], v[6], v[7]);
    }
}

// =====================================================================
// K4: out = LayerNorm2( h1 + W2 ff + b2 )
// smem: W2T[256][132] | ffs[32][256] | h1s[32][128] | b2[128] | g2[128] | bt2[128]
// =====================================================================
__global__ __launch_bounds__(256, 1)
void k4_ffn2(const float* __restrict__ h1, const float* __restrict__ ffv,
             const float* __restrict__ W2, const float* __restrict__ b2,
             const float* __restrict__ ln2g, const float* __restrict__ ln2b,
             float* __restrict__ out)
{
    extern __shared__ float sm[];
    float* W2T = sm;                    // 256*132 = 33792
    float* ffs = W2T + 256 * 132;       // 32*256 = 8192
    float* h1s = ffs + 32 * 256;        // 32*128 = 4096
    float* b2s = h1s + 32 * 128;        // 128
    float* g2  = b2s + 128;             // 128
    float* bt2 = g2 + 128;              // 128
    const int tid = threadIdx.x;

    for (int idx = tid; idx < 128 * 256; idx += 256) {
        int e = idx >> 8, f = idx & 255;
        W2T[f * 132 + e] = W2[idx];
    }
    if (tid < 128) { b2s[tid] = b2[tid]; g2[tid] = ln2g[tid]; bt2[tid] = ln2b[tid]; }
    const int nb0 = blockIdx.x * 32;
    {
        const float4* s4 = (const float4*)(ffv + (size_t)nb0 * 256);
        float4* d4 = (float4*)ffs;
        for (int idx = tid; idx < 32 * 64; idx += 256) d4[idx] = s4[idx];
        const float4* s2 = (const float4*)(h1 + (size_t)nb0 * 128);
        float4* d2 = (float4*)h1s;
        for (int idx = tid; idx < 32 * 32; idx += 256) d2[idx] = s2[idx];
    }
    __syncthreads();

    const int warp = tid >> 5, lane = tid & 31;
    const int nb = warp * 4;
    const int e4 = lane * 4;

    float2 acc[4][2];
#pragma unroll
    for (int j = 0; j < 4; j++) { acc[j][0] = make_float2(0.f, 0.f); acc[j][1] = make_float2(0.f, 0.f); }

#pragma unroll 4
    for (int f = 0; f < 256; f++) {
        float4 wv = *(float4*)(W2T + f * 132 + e4);
        float2 wl = make_float2(wv.x, wv.y), wh = make_float2(wv.z, wv.w);
#pragma unroll
        for (int j = 0; j < 4; j++) {
            float fv = ffs[(nb + j) * 256 + f];
            float2 fd = make_float2(fv, fv);
            acc[j][0] = ffma2(wl, fd, acc[j][0]);
            acc[j][1] = ffma2(wh, fd, acc[j][1]);
        }
    }

    float4 bb = *(float4*)(b2s + e4);
    float4 gg = *(float4*)(g2 + e4);
    float4 tb = *(float4*)(bt2 + e4);
#pragma unroll
    for (int j = 0; j < 4; j++) {
        float4 hv = *(float4*)(h1s + (nb + j) * 128 + e4);
        float r0 = hv.x + acc[j][0].x + bb.x;
        float r1 = hv.y + acc[j][0].y + bb.y;
        float r2 = hv.z + acc[j][1].x + bb.z;
        float r3 = hv.w + acc[j][1].y + bb.w;
        float s  = r0 + r1 + r2 + r3;
        float sq = fmaf(r0, r0, fmaf(r1, r1, fmaf(r2, r2, r3 * r3)));
#pragma unroll
        for (int off = 16; off > 0; off >>= 1) {
            s  += __shfl_xor_sync(0xffffffffu, s, off);
            sq += __shfl_xor_sync(0xffffffffu, sq, off);
        }
        float mu  = s * (1.f / 128.f);
        float var = sq * (1.f / 128.f) - mu * mu;
        float rstd = rsqrtf(var + LN_EPS);
        float o0 = (r0 - mu) * rstd * gg.x + tb.x;
        float o1 = (r1 - mu) * rstd * gg.y + tb.y;
        float o2 = (r2 - mu) * rstd * gg.z + tb.z;
        float o3 = (r3 - mu) * rstd * gg.w + tb.w;
        *(float4*)(out + (size_t)(nb0 + nb + j) * 128 + e4) = make_float4(o0, o1, o2, o3);
    }
}

// =====================================================================
extern "C" void kernel_launch(void* const* d_in, const int* in_sizes, int n_in,
                              void* d_out, int out_size)
{
    const float* x    = (const float*)d_in[0];
    const float* ctx  = (const float*)d_in[1];
    const float* Wq   = (const float*)d_in[2];
    const float* Wk   = (const float*)d_in[3];
    const float* Wv   = (const float*)d_in[4];
    const float* Wo   = (const float*)d_in[5];
    const float* ln1g = (const float*)d_in[6];
    const float* ln1b = (const float*)d_in[7];
    const float* ln2g = (const float*)d_in[8];
    const float* ln2b = (const float*)d_in[9];
    const float* W1   = (const float*)d_in[10];
    const float* b1   = (const float*)d_in[11];
    const float* W2   = (const float*)d_in[12];
    const float* b2   = (const float*)d_in[13];
    float* outp = (float*)d_out;

    float *qt, *h1, *ff;
    cudaGetSymbolAddress((void**)&qt, g_qt);
    cudaGetSymbolAddress((void**)&h1, g_h1);
    cudaGetSymbolAddress((void**)&ff, g_ff);

    const int smem1 = (128 * 132 + 128 * 128 + 32 * 132 + 32 * 128) * 4;                  // 166400
    const int smem2 = (128 * 132 * 2 + 8 * 16 * 132 + 8 * 4 * 132 + 8 * 64 + 8 * 132 + 256) * 4; // 226944
    const int smem3 = (128 * 260 + 32 * 132 + 256) * 4;                                    // 151040
    const int smem4 = (256 * 132 + 32 * 256 + 32 * 128 + 384) * 4;                         // 185856

    cudaFuncSetAttribute(k1_qt,   cudaFuncAttributeMaxDynamicSharedMemorySize, smem1);
    cudaFuncSetAttribute(k2_attn, cudaFuncAttributeMaxDynamicSharedMemorySize, smem2);
    cudaFuncSetAttribute(k3_ffn1, cudaFuncAttributeMaxDynamicSharedMemorySize, smem3);
    cudaFuncSetAttribute(k4_ffn2, cudaFuncAttributeMaxDynamicSharedMemorySize, smem4);

    k1_qt  <<<NNODES / 32, 256, smem1>>>(x, Wq, Wk, qt);
    k2_attn<<<NNODES / 64, 256, smem2>>>(x, ctx, Wv, Wo, ln1g, ln1b, qt, h1);
    k3_ffn1<<<NNODES / 32, 256, smem3>>>(h1, W1, b1, ff);
    k4_ffn2<<<NNODES / 32, 256, smem4>>>(h1, ff, W2, b2, ln2g, ln2b, outp);
}

// round 11
// speedup vs baseline: 1.5756x; 1.5756x over previous
#include <cuda_runtime.h>
#include <math.h>

#define NNODES 65536
#define SCALE 0.17677669529663687f   // 1/sqrt(32)
#define LN_EPS 1e-5f

// ---------------- scratch (static device arrays; no allocation) ----------------
__device__ float g_qt[(size_t)NNODES * 512];   // q~ per node [n][h][e]; overwritten with wctx by k2a
__device__ float g_h1[(size_t)NNODES * 128];   // post-ln1 hidden
__device__ float g_ff[(size_t)NNODES * 256];   // gelu(ffn1)

// ---------------- packed fp32x2 FMA (Blackwell FFMA2, PTX-only) ----------------
__device__ __forceinline__ float2 ffma2(float2 a, float2 b, float2 c) {
    float2 d;
    asm("{\n\t"
        ".reg .b64 ra, rb, rc, rd;\n\t"
        "mov.b64 ra, {%2,%3};\n\t"
        "mov.b64 rb, {%4,%5};\n\t"
        "mov.b64 rc, {%6,%7};\n\t"
        "fma.rn.f32x2 rd, ra, rb, rc;\n\t"
        "mov.b64 {%0,%1}, rd;\n\t"
        "}"
        : "=f"(d.x), "=f"(d.y)
        : "f"(a.x), "f"(a.y), "f"(b.x), "f"(b.y), "f"(c.x), "f"(c.y));
    return d;
}

// =====================================================================
// K1: Q = Wq x ; q~ = SCALE * Wk_h^T Q_h.   512 thr, 16 warps x 4 nodes.
// smem: WqT[128][132] | Wk[128][128] | xs[64][128] | Qs[64][128]  = 198656B
// =====================================================================
__global__ __launch_bounds__(512, 1)
void k1_qt(const float* __restrict__ x, const float* __restrict__ Wq,
           const float* __restrict__ Wk, float* __restrict__ qt)
{
    extern __shared__ float sm[];
    float* WqT = sm;                       // 128*132
    float* Wks = WqT + 128 * 132;          // 128*128
    float* xs  = Wks + 128 * 128;          // 64*128
    float* Qs  = xs + 64 * 128;            // 64*128
    const int tid = threadIdx.x;

    for (int idx = tid; idx < 128 * 128; idx += 512) {
        int o = idx >> 7, i = idx & 127;
        WqT[i * 132 + o] = Wq[idx];
    }
    {
        const float4* s4 = (const float4*)Wk;
        float4* d4 = (float4*)Wks;
        for (int idx = tid; idx < 128 * 128 / 4; idx += 512) d4[idx] = s4[idx];
    }
    const int nb0 = blockIdx.x * 64;
    {
        const float4* x4 = (const float4*)(x + (size_t)nb0 * 128);
        for (int idx = tid; idx < 64 * 32; idx += 512) {
            int n = idx >> 5, c = idx & 31;
            *(float4*)(xs + n * 128 + c * 4) = x4[idx];
        }
    }
    __syncthreads();

    const int warp = tid >> 5, lane = tid & 31;
    const int nb = warp * 4;
    const int o4 = lane * 4;

    // ---- Q = Wq x ----
    float2 acc[4][2];
#pragma unroll
    for (int j = 0; j < 4; j++) { acc[j][0] = make_float2(0.f, 0.f); acc[j][1] = make_float2(0.f, 0.f); }
#pragma unroll 4
    for (int i = 0; i < 128; i++) {
        float4 w = *(float4*)(WqT + i * 132 + o4);
        float2 wl = make_float2(w.x, w.y), wh = make_float2(w.z, w.w);
#pragma unroll
        for (int j = 0; j < 4; j++) {
            float xv = xs[(nb + j) * 128 + i];
            float2 xd = make_float2(xv, xv);
            acc[j][0] = ffma2(wl, xd, acc[j][0]);
            acc[j][1] = ffma2(wh, xd, acc[j][1]);
        }
    }
#pragma unroll
    for (int j = 0; j < 4; j++)
        *(float4*)(Qs + (nb + j) * 128 + o4) =
            make_float4(acc[j][0].x, acc[j][0].y, acc[j][1].x, acc[j][1].y);
    __syncthreads();

    // ---- q~ = SCALE * Wk_h^T Q_h ----
    for (int h = 0; h < 4; h++) {
        float2 a[4][2];
#pragma unroll
        for (int j = 0; j < 4; j++) { a[j][0] = make_float2(0.f, 0.f); a[j][1] = make_float2(0.f, 0.f); }
#pragma unroll 4
        for (int d = 0; d < 32; d++) {
            int o = h * 32 + d;
            float4 w = *(float4*)(Wks + o * 128 + o4);
            float2 wl = make_float2(w.x, w.y), wh = make_float2(w.z, w.w);
#pragma unroll
            for (int j = 0; j < 4; j++) {
                float qv = Qs[(nb + j) * 128 + o];
                float2 qd = make_float2(qv, qv);
                a[j][0] = ffma2(wl, qd, a[j][0]);
                a[j][1] = ffma2(wh, qd, a[j][1]);
            }
        }
#pragma unroll
        for (int j = 0; j < 4; j++) {
            size_t base = ((size_t)(nb0 + nb + j)) * 512 + h * 128 + o4;
            *(float4*)(qt + base) = make_float4(a[j][0].x * SCALE, a[j][0].y * SCALE,
                                                a[j][1].x * SCALE, a[j][1].y * SCALE);
        }
    }
}

// =====================================================================
// K2a: scores -> softmax -> weighted ctx (wctx). No weight matrices.
// 512 thr, 16 warps x 1 node x 8 iters = 128 nodes/CTA.
// ctx tile stored at stride 128 with column swizzle +4*(k>>1) (mod 128):
//   phys[(e + p)&127] = logical[e],  p = 4*(k>>1)
// so row-strided score loads are bank-conflict-free across lanes.
// q~ is stored LINEAR in uw; score loop indexes q at e, ctx at (e+p)&127.
// smem: cs[16][2048] | uw[16][4*132] | ss[16][64] = 168960B
// wctx written IN PLACE over g_qt (q~ fully consumed into uw first).
// =====================================================================
__global__ __launch_bounds__(512, 1)
void k2a_scores(const float* __restrict__ ctx, float* __restrict__ qt)
{
    extern __shared__ float sm[];
    float* cs = sm;                        // 16 * 2048
    float* u  = cs + 16 * 2048;            // 16 * 528
    float* ss = u + 16 * 528;              // 16 * 64
    const int tid = threadIdx.x;
    const int w = tid >> 5, lane = tid & 31;
    float* csw = cs + w * 2048;
    float* uw  = u + w * 528;
    float* ssw = ss + w * 64;

    for (int it = 0; it < 8; it++) {
        const int node = blockIdx.x * 128 + it * 16 + w;

        // load ctx (16x128) with swizzle, q~ (4x128, stride 132, linear)
        const float4* c4 = (const float4*)(ctx + (size_t)node * 2048);
        for (int t = lane; t < 512; t += 32) {
            int k = t >> 5, c = t & 31;
            int col = (c * 4 + 4 * (k >> 1)) & 127;
            *(float4*)(csw + k * 128 + col) = c4[t];
        }
        const float4* q4 = (const float4*)(qt + (size_t)node * 512);
        for (int t = lane; t < 128; t += 32) {
            int h = t >> 5, c = t & 31;
            *(float4*)(uw + h * 132 + c * 4) = q4[t];
        }
        __syncwarp();

        // ---- scores[h][k] (2 k's per lane) ----
        {
            int h = lane >> 3, k0 = (lane & 7) * 2;
            const float* qrow = uw + h * 132;
            const float* c0 = csw + k0 * 128;
            const float* c1 = c0 + 128;
            const int p = 4 * (k0 >> 1);   // same swizzle offset for k0 and k0+1
            float s0 = 0.f, s1 = 0.f;
#pragma unroll 4
            for (int e = 0; e < 128; e++) {
                int ee = (e + p) & 127;        // physical slot of logical element e
                float q = qrow[e];             // q~ is LINEAR (this was the R8 bug)
                s0 = fmaf(q, c0[ee], s0);
                s1 = fmaf(q, c1[ee], s1);
            }
            ssw[h * 16 + k0]     = s0;
            ssw[h * 16 + k0 + 1] = s1;
        }
        __syncwarp();

        // ---- softmax per head (lanes 0..3) ----
        if (lane < 4) {
            float* r = ssw + lane * 16;
            float m = r[0];
#pragma unroll
            for (int k = 1; k < 16; k++) m = fmaxf(m, r[k]);
            float sum = 0.f;
#pragma unroll
            for (int k = 0; k < 16; k++) { float ev = __expf(r[k] - m); r[k] = ev; sum += ev; }
            float inv = 1.f / sum;
#pragma unroll
            for (int k = 0; k < 16; k++) r[k] *= inv;
        }
        __syncwarp();

        // ---- wctx[h][e] = sum_k attn[h][k] ctx[k][e] ----
        float wc[4][4];
#pragma unroll
        for (int h = 0; h < 4; h++)
#pragma unroll
            for (int m = 0; m < 4; m++) wc[h][m] = 0.f;
#pragma unroll
        for (int k = 0; k < 16; k++) {
            const float* crow = csw + k * 128;
            const int pk = 4 * (k >> 1);
            float v0 = crow[(lane + pk) & 127];        // logical ctx[k][lane]
            float v1 = crow[(lane + 32 + pk) & 127];
            float v2 = crow[(lane + 64 + pk) & 127];
            float v3 = crow[(lane + 96 + pk) & 127];
#pragma unroll
            for (int h = 0; h < 4; h++) {
                float a = ssw[h * 16 + k];
                wc[h][0] = fmaf(a, v0, wc[h][0]);
                wc[h][1] = fmaf(a, v1, wc[h][1]);
                wc[h][2] = fmaf(a, v2, wc[h][2]);
                wc[h][3] = fmaf(a, v3, wc[h][3]);
            }
        }
        // write wctx over qt[node] (stride 128, linear)
        float* qo = qt + (size_t)node * 512;
#pragma unroll
        for (int h = 0; h < 4; h++) {
            qo[h * 128 + lane]      = wc[h][0];
            qo[h * 128 + lane + 32] = wc[h][1];
            qo[h * 128 + lane + 64] = wc[h][2];
            qo[h * 128 + lane + 96] = wc[h][3];
        }
        __syncwarp();
    }
}

// =====================================================================
// K2b: v = Wv_h wctx_h ; attnout = Wo v ; +x ; LayerNorm1 -> h1
// 512 thr, 16 warps x 2 nodes x 4 iters = 128 nodes/CTA.
// smem: WvT[128][132] | WoT[128][132] | wbuf[16][2][4*132] | osw[16][2][128]
//       | ln params = 220160B
// =====================================================================
__global__ __launch_bounds__(512, 1)
void k2b_proj(const float* __restrict__ x, const float* __restrict__ Wv,
              const float* __restrict__ Wo, const float* __restrict__ ln1g,
              const float* __restrict__ ln1b, const float* __restrict__ wctx,
              float* __restrict__ h1out)
{
    extern __shared__ float sm[];
    float* WvT = sm;                         // 128*132
    float* WoT = WvT + 128 * 132;            // 128*132
    float* wb  = WoT + 128 * 132;            // 16*2*528
    float* os  = wb + 16 * 1056;             // 16*2*128
    float* lg  = os + 16 * 256;              // 128
    float* lb  = lg + 128;                   // 128
    const int tid = threadIdx.x;

    for (int idx = tid; idx < 128 * 128; idx += 512) {
        int o = idx >> 7, e = idx & 127;
        WvT[e * 132 + o] = Wv[idx];
        WoT[e * 132 + o] = Wo[idx];
    }
    if (tid < 128) { lg[tid] = ln1g[tid]; lb[tid] = ln1b[tid]; }
    __syncthreads();

    const int w = tid >> 5, lane = tid & 31;
    float* wbw = wb + w * 1056;
    float* osw = os + w * 256;
    const int o4 = lane * 4;
    const int ho = lane >> 3;

    for (int it = 0; it < 4; it++) {
        const int n0 = blockIdx.x * 128 + it * 32 + w * 2;

        // load wctx for 2 nodes into padded smem rows (h stride 132)
#pragma unroll
        for (int j = 0; j < 2; j++) {
            const float4* s4 = (const float4*)(wctx + (size_t)(n0 + j) * 512);
            for (int t = lane; t < 128; t += 32) {
                int h = t >> 5, c = t & 31;
                *(float4*)(wbw + j * 528 + h * 132 + c * 4) = s4[t];
            }
        }
        __syncwarp();

        // ---- v[o] = sum_e Wv[o][e] * wctx[ho][e] ----
        float2 a0[2], a1[2];
#pragma unroll
        for (int j = 0; j < 2; j++) { a0[j] = make_float2(0.f, 0.f); a1[j] = make_float2(0.f, 0.f); }
#pragma unroll 4
        for (int e = 0; e < 128; e++) {
            float4 wv = *(float4*)(WvT + e * 132 + o4);
            float2 wl = make_float2(wv.x, wv.y), wh = make_float2(wv.z, wv.w);
#pragma unroll
            for (int j = 0; j < 2; j++) {
                float wcv = wbw[j * 528 + ho * 132 + e];
                float2 wd = make_float2(wcv, wcv);
                a0[j] = ffma2(wl, wd, a0[j]);
                a1[j] = ffma2(wh, wd, a1[j]);
            }
        }
#pragma unroll
        for (int j = 0; j < 2; j++)
            *(float4*)(osw + j * 128 + o4) = make_float4(a0[j].x, a0[j].y, a1[j].x, a1[j].y);
        __syncwarp();

        // ---- attnout = Wo v ; residual + LN1 ----
        float2 b0[2], b1[2];
#pragma unroll
        for (int j = 0; j < 2; j++) { b0[j] = make_float2(0.f, 0.f); b1[j] = make_float2(0.f, 0.f); }
#pragma unroll 4
        for (int jj = 0; jj < 128; jj++) {
            float4 wo = *(float4*)(WoT + jj * 132 + o4);
            float2 wl = make_float2(wo.x, wo.y), wh = make_float2(wo.z, wo.w);
#pragma unroll
            for (int j = 0; j < 2; j++) {
                float ov = osw[j * 128 + jj];
                float2 od = make_float2(ov, ov);
                b0[j] = ffma2(wl, od, b0[j]);
                b1[j] = ffma2(wh, od, b1[j]);
            }
        }
        float4 gv = *(float4*)(lg + o4);
        float4 bv = *(float4*)(lb + o4);
#pragma unroll
        for (int j = 0; j < 2; j++) {
            const int node = n0 + j;
            float4 xv = *(const float4*)(x + (size_t)node * 128 + o4);
            float r0 = xv.x + b0[j].x, r1 = xv.y + b0[j].y;
            float r2 = xv.z + b1[j].x, r3 = xv.w + b1[j].y;
            float s  = r0 + r1 + r2 + r3;
            float sq = fmaf(r0, r0, fmaf(r1, r1, fmaf(r2, r2, r3 * r3)));
#pragma unroll
            for (int off = 16; off > 0; off >>= 1) {
                s  += __shfl_xor_sync(0xffffffffu, s, off);
                sq += __shfl_xor_sync(0xffffffffu, sq, off);
            }
            float mu  = s * (1.f / 128.f);
            float var = sq * (1.f / 128.f) - mu * mu;
            float rstd = rsqrtf(var + LN_EPS);
            float h0 = (r0 - mu) * rstd * gv.x + bv.x;
            float h1v = (r1 - mu) * rstd * gv.y + bv.y;
            float h2 = (r2 - mu) * rstd * gv.z + bv.z;
            float h3 = (r3 - mu) * rstd * gv.w + bv.w;
            *(float4*)(h1out + (size_t)node * 128 + o4) = make_float4(h0, h1v, h2, h3);
        }
        __syncwarp();
    }
}

// =====================================================================
// K3: ff = gelu(W1 h1 + b1).  512 thr, 16 warps x 8 nodes = 128 nodes/CTA.
// smem: W1T[128][260] | h1s[128][128] | b1[256] = 199680B
// =====================================================================
__global__ __launch_bounds__(512, 1)
void k3_ffn1(const float* __restrict__ h1, const float* __restrict__ W1,
             const float* __restrict__ b1, float* __restrict__ ff)
{
    extern __shared__ float sm[];
    float* W1T = sm;                   // 128*260
    float* h1s = W1T + 128 * 260;      // 128*128
    float* b1s = h1s + 128 * 128;      // 256
    const int tid = threadIdx.x;

    for (int idx = tid; idx < 256 * 128; idx += 512) {
        int f = idx >> 7, e = idx & 127;
        W1T[e * 260 + f] = W1[idx];
    }
    if (tid < 256) b1s[tid] = b1[tid];
    const int nb0 = blockIdx.x * 128;
    {
        const float4* s4 = (const float4*)(h1 + (size_t)nb0 * 128);
        for (int idx = tid; idx < 128 * 32; idx += 512) {
            int n = idx >> 5, c = idx & 31;
            *(float4*)(h1s + n * 128 + c * 4) = s4[idx];
        }
    }
    __syncthreads();

    const int warp = tid >> 5, lane = tid & 31;
    const int nb = warp * 8;
    const int f4 = lane * 4;

    float2 acc[8][4];
#pragma unroll
    for (int j = 0; j < 8; j++)
#pragma unroll
        for (int m = 0; m < 4; m++) acc[j][m] = make_float2(0.f, 0.f);

#pragma unroll 2
    for (int e = 0; e < 128; e++) {
        float4 wa = *(float4*)(W1T + e * 260 + f4);
        float4 wb = *(float4*)(W1T + e * 260 + f4 + 128);
        float2 al = make_float2(wa.x, wa.y), ah = make_float2(wa.z, wa.w);
        float2 bl = make_float2(wb.x, wb.y), bh = make_float2(wb.z, wb.w);
#pragma unroll
        for (int j = 0; j < 8; j++) {
            float hv = h1s[(nb + j) * 128 + e];
            float2 hd = make_float2(hv, hv);
            acc[j][0] = ffma2(al, hd, acc[j][0]);
            acc[j][1] = ffma2(ah, hd, acc[j][1]);
            acc[j][2] = ffma2(bl, hd, acc[j][2]);
            acc[j][3] = ffma2(bh, hd, acc[j][3]);
        }
    }

#pragma unroll
    for (int j = 0; j < 8; j++) {
        float v[8];
        v[0] = acc[j][0].x + b1s[f4];       v[1] = acc[j][0].y + b1s[f4 + 1];
        v[2] = acc[j][1].x + b1s[f4 + 2];   v[3] = acc[j][1].y + b1s[f4 + 3];
        v[4] = acc[j][2].x + b1s[f4 + 128]; v[5] = acc[j][2].y + b1s[f4 + 129];
        v[6] = acc[j][3].x + b1s[f4 + 130]; v[7] = acc[j][3].y + b1s[f4 + 131];
#pragma unroll
        for (int m = 0; m < 8; m++)
            v[m] = 0.5f * v[m] * (1.0f + erff(v[m] * 0.70710678118654752f));
        size_t base = (size_t)(nb0 + nb + j) * 256;
        *(float4*)(ff + base + f4)       = make_float4(v[0], v[1], v[2], v[3]);
        *(float4*)(ff + base + f4 + 128) = make_float4(v[4], v[5], v[6], v[7]);
    }
}

// =====================================================================
// K4: out = LN2(h1 + W2 ff + b2). 512 thr, 2 phases x 64 nodes = 128/CTA.
// smem: W2T[256][132] | ffs[64][256] | b2/g2/bt2 = 202240B. h1 read from gmem.
// =====================================================================
__global__ __launch_bounds__(512, 1)
void k4_ffn2(const float* __restrict__ h1, const float* __restrict__ ffv,
             const float* __restrict__ W2, const float* __restrict__ b2,
             const float* __restrict__ ln2g, const float* __restrict__ ln2b,
             float* __restrict__ out)
{
    extern __shared__ float sm[];
    float* W2T = sm;                    // 256*132
    float* ffs = W2T + 256 * 132;       // 64*256
    float* b2s = ffs + 64 * 256;        // 128
    float* g2  = b2s + 128;             // 128
    float* bt2 = g2 + 128;              // 128
    const int tid = threadIdx.x;

    for (int idx = tid; idx < 128 * 256; idx += 512) {
        int e = idx >> 8, f = idx & 255;
        W2T[f * 132 + e] = W2[idx];
    }
    if (tid < 128) { b2s[tid] = b2[tid]; g2[tid] = ln2g[tid]; bt2[tid] = ln2b[tid]; }

    const int warp = tid >> 5, lane = tid & 31;
    const int e4 = lane * 4;
    const int nb0 = blockIdx.x * 128;

    for (int p = 0; p < 2; p++) {
        __syncthreads();
        {
            const float4* s4 = (const float4*)(ffv + (size_t)(nb0 + p * 64) * 256);
            float4* d4 = (float4*)ffs;
            for (int idx = tid; idx < 64 * 64; idx += 512) d4[idx] = s4[idx];
        }
        __syncthreads();

        const int nl = warp * 4;   // local node base within phase
        float2 acc[4][2];
#pragma unroll
        for (int j = 0; j < 4; j++) { acc[j][0] = make_float2(0.f, 0.f); acc[j][1] = make_float2(0.f, 0.f); }

#pragma unroll 4
        for (int f = 0; f < 256; f++) {
            float4 wv = *(float4*)(W2T + f * 132 + e4);
            float2 wl = make_float2(wv.x, wv.y), wh = make_float2(wv.z, wv.w);
#pragma unroll
            for (int j = 0; j < 4; j++) {
                float fv = ffs[(nl + j) * 256 + f];
                float2 fd = make_float2(fv, fv);
                acc[j][0] = ffma2(wl, fd, acc[j][0]);
                acc[j][1] = ffma2(wh, fd, acc[j][1]);
            }
        }

        float4 bb = *(float4*)(b2s + e4);
        float4 gg = *(float4*)(g2 + e4);
        float4 tb = *(float4*)(bt2 + e4);
#pragma unroll
        for (int j = 0; j < 4; j++) {
            const int node = nb0 + p * 64 + nl + j;
            float4 hv = *(const float4*)(h1 + (size_t)node * 128 + e4);
            float r0 = hv.x + acc[j][0].x + bb.x;
            float r1 = hv.y + acc[j][0].y + bb.y;
            float r2 = hv.z + acc[j][1].x + bb.z;
            float r3 = hv.w + acc[j][1].y + bb.w;
            float s  = r0 + r1 + r2 + r3;
            float sq = fmaf(r0, r0, fmaf(r1, r1, fmaf(r2, r2, r3 * r3)));
#pragma unroll
            for (int off = 16; off > 0; off >>= 1) {
                s  += __shfl_xor_sync(0xffffffffu, s, off);
                sq += __shfl_xor_sync(0xffffffffu, sq, off);
            }
            float mu  = s * (1.f / 128.f);
            float var = sq * (1.f / 128.f) - mu * mu;
            float rstd = rsqrtf(var + LN_EPS);
            float o0 = (r0 - mu) * rstd * gg.x + tb.x;
            float o1 = (r1 - mu) * rstd * gg.y + tb.y;
            float o2 = (r2 - mu) * rstd * gg.z + tb.z;
            float o3 = (r3 - mu) * rstd * gg.w + tb.w;
            *(float4*)(out + (size_t)node * 128 + e4) = make_float4(o0, o1, o2, o3);
        }
    }
}

// =====================================================================
extern "C" void kernel_launch(void* const* d_in, const int* in_sizes, int n_in,
                              void* d_out, int out_size)
{
    const float* x    = (const float*)d_in[0];
    const float* ctx  = (const float*)d_in[1];
    const float* Wq   = (const float*)d_in[2];
    const float* Wk   = (const float*)d_in[3];
    const float* Wv   = (const float*)d_in[4];
    const float* Wo   = (const float*)d_in[5];
    const float* ln1g = (const float*)d_in[6];
    const float* ln1b = (const float*)d_in[7];
    const float* ln2g = (const float*)d_in[8];
    const float* ln2b = (const float*)d_in[9];
    const float* W1   = (const float*)d_in[10];
    const float* b1   = (const float*)d_in[11];
    const float* W2   = (const float*)d_in[12];
    const float* b2   = (const float*)d_in[13];
    float* outp = (float*)d_out;

    float *qt, *h1, *ff;
    cudaGetSymbolAddress((void**)&qt, g_qt);
    cudaGetSymbolAddress((void**)&h1, g_h1);
    cudaGetSymbolAddress((void**)&ff, g_ff);

    const int smem1  = (128 * 132 + 128 * 128 + 64 * 128 + 64 * 128) * 4;   // 198656
    const int smem2a = (16 * 2048 + 16 * 528 + 16 * 64) * 4;                // 168960
    const int smem2b = (128 * 132 * 2 + 16 * 1056 + 16 * 256 + 256) * 4;    // 220160
    const int smem3  = (128 * 260 + 128 * 128 + 256) * 4;                   // 199680
    const int smem4  = (256 * 132 + 64 * 256 + 384) * 4;                    // 202240

    cudaFuncSetAttribute(k1_qt,      cudaFuncAttributeMaxDynamicSharedMemorySize, smem1);
    cudaFuncSetAttribute(k2a_scores, cudaFuncAttributeMaxDynamicSharedMemorySize, smem2a);
    cudaFuncSetAttribute(k2b_proj,   cudaFuncAttributeMaxDynamicSharedMemorySize, smem2b);
    cudaFuncSetAttribute(k3_ffn1,    cudaFuncAttributeMaxDynamicSharedMemorySize, smem3);
    cudaFuncSetAttribute(k4_ffn2,    cudaFuncAttributeMaxDynamicSharedMemorySize, smem4);

    k1_qt      <<<NNODES / 64,  512, smem1>>>(x, Wq, Wk, qt);
    k2a_scores <<<NNODES / 128, 512, smem2a>>>(ctx, qt);
    k2b_proj   <<<NNODES / 128, 512, smem2b>>>(x, Wv, Wo, ln1g, ln1b, qt, h1);
    k3_ffn1    <<<NNODES / 128, 512, smem3>>>(h1, W1, b1, ff);
    k4_ffn2    <<<NNODES / 128, 512, smem4>>>(h1, ff, W2, b2, ln2g, ln2b, outp);
}